// round 1
// baseline (speedup 1.0000x reference)
#include <cuda_runtime.h>
#include <math.h>

#define NR 12288
#define KD 512
#define FD 128
#define NB 8192
#define BLO (-6.0f)
#define BHI (6.0f)
#define NCH 96
#define CH 128

// ---------------- device scratch (no allocs allowed) ----------------
__device__ float g_w[FD * KD];
__device__ float g_z[NR * FD];
__device__ float g_s[NR];
__device__ float g_t[NR];
__device__ int   g_cnt[NB];
__device__ int   g_bstart[NB + 1];
__device__ int   g_cursor[NB];
__device__ int   g_perm[NR];
__device__ float g_tp[NR];
__device__ float g_chZ[NCH * FD];
__device__ float g_chEZ[NCH * FD];
__device__ float g_chE[NCH];
__device__ float g_ofZ[NCH * FD];
__device__ float g_ofEZ[NCH * FD];
__device__ float g_ofE[NCH];
__device__ float g_PZ[(NR + 1) * FD];
__device__ float g_SEZ[(NR + 1) * FD];
__device__ float g_SE[NR + 1];

__device__ __forceinline__ int bucket_of(float t) {
    float u = (t - BLO) * ((float)NB / (BHI - BLO));
    int b = (int)floorf(u);
    b = b < 0 ? 0 : b;
    b = b > NB - 1 ? NB - 1 : b;
    return b;
}

// ---------------- 1. weight-norm: w = g * v / ||v|| ----------------
__global__ void k_w(const float* __restrict__ v, const float* __restrict__ g) {
    int r = blockIdx.x, t = threadIdx.x;
    float ss = 0.f;
    for (int c = t; c < KD; c += 128) { float a = v[r * KD + c]; ss += a * a; }
    __shared__ float red[4];
    #pragma unroll
    for (int o = 16; o; o >>= 1) ss += __shfl_xor_sync(0xffffffffu, ss, o);
    if ((t & 31) == 0) red[t >> 5] = ss;
    __syncthreads();
    float tot = red[0] + red[1] + red[2] + red[3];
    float sc = g[r] / sqrtf(tot);
    for (int c = t; c < KD; c += 128) g_w[r * KD + c] = v[r * KD + c] * sc;
}

// ---------------- 2. GEMM: z[NR,128] = x[NR,512] @ w^T + b ----------------
// tile 32(M) x 128(N) x 16(K), 128 threads, 4x8 microtile
__global__ void k_gemm(const float* __restrict__ x, const float* __restrict__ b) {
    __shared__ float As[16][32];
    __shared__ float Bs[16][128];
    int tid = threadIdx.x;
    int m0 = blockIdx.x * 32;
    int ty = tid >> 4, tx = tid & 15;
    int arow = tid >> 2, aseg = tid & 3;

    float acc[4][8];
    #pragma unroll
    for (int i = 0; i < 4; i++)
        #pragma unroll
        for (int j = 0; j < 8; j++) acc[i][j] = 0.f;

    for (int k0 = 0; k0 < KD; k0 += 16) {
        float4 av = *(const float4*)(x + (size_t)(m0 + arow) * KD + k0 + aseg * 4);
        As[aseg * 4 + 0][arow] = av.x;
        As[aseg * 4 + 1][arow] = av.y;
        As[aseg * 4 + 2][arow] = av.z;
        As[aseg * 4 + 3][arow] = av.w;
        #pragma unroll
        for (int l = 0; l < 4; l++) {
            int e = tid + l * 128;
            int brow = e >> 2, bseg = e & 3;
            float4 bv = *(const float4*)(g_w + (size_t)brow * KD + k0 + bseg * 4);
            Bs[bseg * 4 + 0][brow] = bv.x;
            Bs[bseg * 4 + 1][brow] = bv.y;
            Bs[bseg * 4 + 2][brow] = bv.z;
            Bs[bseg * 4 + 3][brow] = bv.w;
        }
        __syncthreads();
        #pragma unroll
        for (int kk = 0; kk < 16; kk++) {
            float4 a4 = *(float4*)(&As[kk][ty * 4]);
            float4 b0 = *(float4*)(&Bs[kk][tx * 4]);
            float4 b1 = *(float4*)(&Bs[kk][64 + tx * 4]);
            float ar[4] = {a4.x, a4.y, a4.z, a4.w};
            float br[8] = {b0.x, b0.y, b0.z, b0.w, b1.x, b1.y, b1.z, b1.w};
            #pragma unroll
            for (int im = 0; im < 4; im++)
                #pragma unroll
                for (int in = 0; in < 8; in++)
                    acc[im][in] = fmaf(ar[im], br[in], acc[im][in]);
        }
        __syncthreads();
    }
    float4 bb0 = *(const float4*)(b + tx * 4);
    float4 bb1 = *(const float4*)(b + 64 + tx * 4);
    #pragma unroll
    for (int im = 0; im < 4; im++) {
        int row = m0 + ty * 4 + im;
        float4 o0 = make_float4(acc[im][0] + bb0.x, acc[im][1] + bb0.y,
                                acc[im][2] + bb0.z, acc[im][3] + bb0.w);
        float4 o1 = make_float4(acc[im][4] + bb1.x, acc[im][5] + bb1.y,
                                acc[im][6] + bb1.z, acc[im][7] + bb1.w);
        *(float4*)(g_z + (size_t)row * FD + tx * 4) = o0;
        *(float4*)(g_z + (size_t)row * FD + 64 + tx * 4) = o1;
    }
}

// ---------------- 3. s = z@a_src, t = z@a_dst (one warp per row) ----------------
__global__ void k_st(const float* __restrict__ att) {
    int gw = (blockIdx.x * blockDim.x + threadIdx.x) >> 5;
    int lane = threadIdx.x & 31;
    if (gw >= NR) return;
    const float* zr = g_z + (size_t)gw * FD;
    float s = 0.f, t = 0.f;
    #pragma unroll
    for (int q = 0; q < 4; q++) {
        float zv = zr[lane + 32 * q];
        s += zv * att[lane + 32 * q];
        t += zv * att[FD + lane + 32 * q];
    }
    #pragma unroll
    for (int o = 16; o; o >>= 1) {
        s += __shfl_xor_sync(0xffffffffu, s, o);
        t += __shfl_xor_sync(0xffffffffu, t, o);
    }
    if (lane == 0) { g_s[gw] = s; g_t[gw] = t; }
}

// ---------------- 4. bucket counting sort of t ----------------
__global__ void k_zero() {
    int i = blockIdx.x * 256 + threadIdx.x;
    if (i < NB) g_cnt[i] = 0;
}

__global__ void k_hist() {
    int j = blockIdx.x * 256 + threadIdx.x;
    if (j < NR) atomicAdd(&g_cnt[bucket_of(g_t[j])], 1);
}

__global__ void k_prefix() {
    __shared__ int part[256];
    int t = threadIdx.x;
    int base = t * 32;
    int s = 0;
    for (int i = 0; i < 32; i++) s += g_cnt[base + i];
    part[t] = s;
    __syncthreads();
    if (t == 0) {
        int run = 0;
        for (int i = 0; i < 256; i++) { int c = part[i]; part[i] = run; run += c; }
    }
    __syncthreads();
    int run = part[t];
    for (int i = 0; i < 32; i++) {
        g_bstart[base + i] = run;
        g_cursor[base + i] = run;
        run += g_cnt[base + i];
    }
    if (t == 255) g_bstart[NB] = NR;
}

__global__ void k_scatter() {
    int j = blockIdx.x * 256 + threadIdx.x;
    if (j >= NR) return;
    float tv = g_t[j];
    int b = bucket_of(tv);
    int slot = atomicAdd(&g_cursor[b], 1);
    g_perm[slot] = j;
    g_tp[slot] = tv;
}

// ---------------- 5. chunked scans over bucket-ordered z rows ----------------
__global__ void k_s1() {
    int c = blockIdx.x, f = threadIdx.x;
    int base = c * CH;
    float aZ = 0.f, aEZ = 0.f, aE = 0.f;
    #pragma unroll 4
    for (int r = 0; r < CH; r++) {
        int m = base + r;
        float et = expf(g_tp[m]);
        float zv = g_z[(size_t)g_perm[m] * FD + f];
        aZ += zv;
        aEZ = fmaf(et, zv, aEZ);
        aE += et;
    }
    g_chZ[c * FD + f] = aZ;
    g_chEZ[c * FD + f] = aEZ;
    if (f == 0) g_chE[c] = aE;
}

__global__ void k_s2() {
    int f = threadIdx.x;
    float run = 0.f;
    for (int c = 0; c < NCH; c++) { g_ofZ[c * FD + f] = run; run += g_chZ[c * FD + f]; }
    g_PZ[(size_t)NR * FD + f] = run;
    float re = 0.f;
    for (int c = NCH - 1; c >= 0; c--) { g_ofEZ[c * FD + f] = re; re += g_chEZ[c * FD + f]; }
    g_SEZ[(size_t)NR * FD + f] = 0.f;
    if (f == 0) {
        float rE = 0.f;
        for (int c = NCH - 1; c >= 0; c--) { g_ofE[c] = rE; rE += g_chE[c]; }
        g_SE[NR] = 0.f;
    }
}

__global__ void k_s3() {
    int c = blockIdx.x, f = threadIdx.x, base = c * CH;
    float aZ = g_ofZ[c * FD + f];
    #pragma unroll 4
    for (int r = 0; r < CH; r++) {
        int m = base + r;
        g_PZ[(size_t)m * FD + f] = aZ;
        aZ += g_z[(size_t)g_perm[m] * FD + f];
    }
    float aEZ = g_ofEZ[c * FD + f];
    float aE = g_ofE[c];
    #pragma unroll 4
    for (int r = CH - 1; r >= 0; r--) {
        int m = base + r;
        float et = expf(g_tp[m]);
        aEZ = fmaf(et, g_z[(size_t)g_perm[m] * FD + f], aEZ);
        g_SEZ[(size_t)m * FD + f] = aEZ;
        if (f == 0) { aE += et; g_SE[m] = aE; }
    }
}

// ---------------- 6. per-row combine + boundary bucket + row softmax ----------------
__global__ void k_final(float* __restrict__ out) {
    __shared__ float rmax[4], rsum[4];
    int f = threadIdx.x, lane = f & 31, wid = f >> 5;
    #pragma unroll 1
    for (int rr = 0; rr < 4; rr++) {
        int i = blockIdx.x * 4 + rr;
        float si = g_s[i];
        float th = -si;
        float es = expf(si);
        int b = bucket_of(th);
        int klo = g_bstart[b], khi = g_bstart[b + 1];
        float D = (float)klo + es * g_SE[khi];
        float num = g_PZ[(size_t)klo * FD + f] + es * g_SEZ[(size_t)khi * FD + f];
        for (int m = klo; m < khi; m++) {
            float tj = g_tp[m];
            float zv = g_z[(size_t)g_perm[m] * FD + f];
            if (tj <= th) { num += zv; D += 1.f; }
            else { float w = es * expf(tj); num = fmaf(w, zv, num); D += w; }
        }
        float z2 = num / D + g_z[(size_t)i * FD + f];
        // softmax over 128 features
        float mx = z2;
        #pragma unroll
        for (int o = 16; o; o >>= 1) mx = fmaxf(mx, __shfl_xor_sync(0xffffffffu, mx, o));
        if (lane == 0) rmax[wid] = mx;
        __syncthreads();
        mx = fmaxf(fmaxf(rmax[0], rmax[1]), fmaxf(rmax[2], rmax[3]));
        float ex = expf(z2 - mx);
        float sm = ex;
        #pragma unroll
        for (int o = 16; o; o >>= 1) sm += __shfl_xor_sync(0xffffffffu, sm, o);
        if (lane == 0) rsum[wid] = sm;
        __syncthreads();
        sm = rsum[0] + rsum[1] + rsum[2] + rsum[3];
        out[(size_t)i * FD + f] = ex / sm;
    }
}

// ---------------- launch ----------------
extern "C" void kernel_launch(void* const* d_in, const int* in_sizes, int n_in,
                              void* d_out, int out_size) {
    const float* x   = (const float*)d_in[0];
    const float* v   = (const float*)d_in[1];
    const float* g   = (const float*)d_in[2];
    const float* b   = (const float*)d_in[3];
    const float* att = (const float*)d_in[4];
    float* out = (float*)d_out;

    k_w<<<FD, 128>>>(v, g);
    k_gemm<<<NR / 32, 128>>>(x, b);
    k_st<<<NR / 8, 256>>>(att);
    k_zero<<<NB / 256, 256>>>();
    k_hist<<<NR / 256, 256>>>();
    k_prefix<<<1, 256>>>();
    k_scatter<<<NR / 256, 256>>>();
    k_s1<<<NCH, FD>>>();
    k_s2<<<1, FD>>>();
    k_s3<<<NCH, FD>>>();
    k_final<<<NR / 4, FD>>>(out);
}